// round 11
// baseline (speedup 1.0000x reference)
#include <cuda_runtime.h>
#include <cstdint>
#include <cmath>

#define LQ 2048
#define DIM 1536
#define NH 12
#define HD 128
#define SCALE 0.08838834764831845f   // 128^-0.5
#define NSLICE 3
#define KSLICE (DIM / NSLICE)         // 512  (Eigen gebp kc panel)

// ---------------- scratch (static device globals; no allocation) ----------------
__device__ float g_Qf[NH * LQ * HD];
__device__ float g_Kf[NH * LQ * HD];
__device__ float g_Vf[NH * LQ * HD];
__device__ float g_S[(size_t)NH * LQ * LQ];   // scores, 201MB
__device__ float g_M[NH * LQ];
__device__ float g_Z[NH * LQ];
__device__ float g_attnO[LQ * DIM];
__device__ unsigned int g_amax[4];
__device__ unsigned int g_minZ;

__global__ void init_kernel() {
    if (threadIdx.x < 4) g_amax[threadIdx.x] = 0u;
    if (threadIdx.x == 0) g_minZ = 0x7f800000u;  // +inf
}

// ------ 3-panel fp32 projection: C = A[2048,1536] @ B[1536,1536]^T ---------------
// Per output element: three serial-ascending fp32 FMA chains over contiguous
// 512-length K panels, combined serially in panel order (Eigen gebp emulation).
// BM=128, BN=64, BK=8; 256 threads; thread tile 8x4.
// mode 0 -> g_Qf, 1 -> g_Kf, 2 -> g_Vf (head layout) + exact amax reduce.
__global__ __launch_bounds__(256) void proj_kernel(
    const float* __restrict__ A, const float* __restrict__ B, int mode)
{
    const int K = DIM;
    __shared__ float As[8][132];
    __shared__ float Bs[8][68];

    int tid = threadIdx.x;
    int tx = tid & 15, ty = tid >> 4;
    int row0 = blockIdx.y * 128, col0 = blockIdx.x * 64;

    int ar = tid >> 1, akc = (tid & 1) * 4;      // A: 128 rows x 8 k
    int br = tid >> 1, bkc = (tid & 1) * 4;      // B: 64 rows x 8 k (first 128 thr)

    float comb[8][4];                            // running panel-combined result
    float acc[8][4];                             // current panel accumulator

#pragma unroll 1
    for (int s = 0; s < NSLICE; s++) {
#pragma unroll
        for (int i = 0; i < 8; i++)
#pragma unroll
            for (int j = 0; j < 4; j++) acc[i][j] = 0.f;

        int kbeg = s * KSLICE, kend = kbeg + KSLICE;
        for (int k0 = kbeg; k0 < kend; k0 += 8) {
            __syncthreads();
            {
                float4 a4 = *(const float4*)(A + (size_t)(row0 + ar) * K + k0 + akc);
                As[akc + 0][ar] = a4.x; As[akc + 1][ar] = a4.y;
                As[akc + 2][ar] = a4.z; As[akc + 3][ar] = a4.w;
            }
            if (tid < 128) {
                float4 b4 = *(const float4*)(B + (size_t)(col0 + br) * K + k0 + bkc);
                Bs[bkc + 0][br] = b4.x; Bs[bkc + 1][br] = b4.y;
                Bs[bkc + 2][br] = b4.z; Bs[bkc + 3][br] = b4.w;
            }
            __syncthreads();
#pragma unroll
            for (int kk = 0; kk < 8; kk++) {
                float a[8], b[4];
#pragma unroll
                for (int i = 0; i < 8; i++) a[i] = As[kk][ty * 8 + i];
#pragma unroll
                for (int j = 0; j < 4; j++) b[j] = Bs[kk][tx * 4 + j];
#pragma unroll
                for (int i = 0; i < 8; i++)
#pragma unroll
                    for (int j = 0; j < 4; j++)
                        acc[i][j] = fmaf(a[i], b[j], acc[i][j]);
            }
        }

        if (s == 0) {
#pragma unroll
            for (int i = 0; i < 8; i++)
#pragma unroll
                for (int j = 0; j < 4; j++) comb[i][j] = acc[i][j];
        } else {
#pragma unroll
            for (int i = 0; i < 8; i++)
#pragma unroll
                for (int j = 0; j < 4; j++) comb[i][j] += acc[i][j];
        }
    }

    float* dst = (mode == 0) ? g_Qf : (mode == 1) ? g_Kf : g_Vf;
    float lmax = 0.f;
#pragma unroll
    for (int i = 0; i < 8; i++) {
        int r = row0 + ty * 8 + i;
#pragma unroll
        for (int j = 0; j < 4; j++) {
            int c = col0 + tx * 4 + j;
            float v = comb[i][j];
            int h = c >> 7, d = c & 127;
            dst[((size_t)h * LQ + r) * HD + d] = v;
            lmax = fmaxf(lmax, fabsf(v));
        }
    }
#pragma unroll
    for (int off = 16; off; off >>= 1)
        lmax = fmaxf(lmax, __shfl_xor_sync(0xffffffffu, lmax, off));
    if ((tid & 31) == 0)
        atomicMax(&g_amax[mode], __float_as_uint(lmax));
}

// ------- quantize Q,K,V in place (IEEE RN divisions, round-half-even) ------------
__global__ void quant_all() {
    float sQ = __fdiv_rn(__uint_as_float(g_amax[0]), 127.0f);
    float sK = __fdiv_rn(__uint_as_float(g_amax[1]), 127.0f);
    float sV = __fdiv_rn(__uint_as_float(g_amax[2]), 127.0f);
    int idx = blockIdx.x * 256 + threadIdx.x;

    float q = g_Qf[idx];
    float qi = rintf(__fdiv_rn(q, sQ));
    qi = fmaxf(-128.f, fminf(127.f, qi));
    g_Qf[idx] = qi * sQ;

    float k = g_Kf[idx];
    float ki = rintf(__fdiv_rn(k, sK));
    ki = fmaxf(-128.f, fminf(127.f, ki));
    g_Kf[idx] = ki * sK;

    float v = g_Vf[idx];
    float vi = rintf(__fdiv_rn(v, sV));
    vi = fmaxf(-128.f, fminf(127.f, vi));
    g_Vf[idx] = vi * sV;
}

// ------ scores: strict serial-ascending fp32 FMA chain over d (single panel) -----
// grid (LQ/64 k, LQ/64 q, NH), 256 threads, 4x4/thread
__global__ __launch_bounds__(256) void score_kernel() {
    __shared__ float Qs[8][68];
    __shared__ float Ks[8][68];

    int h = blockIdx.z;
    int q0 = blockIdx.y * 64, k0g = blockIdx.x * 64;
    int tid = threadIdx.x;
    int tx = tid & 15, ty = tid >> 4;
    const float* Qg = g_Qf + ((size_t)h * LQ + q0) * HD;
    const float* Kg = g_Kf + ((size_t)h * LQ + k0g) * HD;

    float acc[4][4];
#pragma unroll
    for (int i = 0; i < 4; i++)
#pragma unroll
        for (int j = 0; j < 4; j++) acc[i][j] = 0.f;

    for (int d0 = 0; d0 < HD; d0 += 8) {
        __syncthreads();
#pragma unroll
        for (int t = 0; t < 2; t++) {
            int i = tid + t * 256;
            int r = i >> 3, c = i & 7;
            Qs[c][r] = Qg[(size_t)r * HD + d0 + c];
            Ks[c][r] = Kg[(size_t)r * HD + d0 + c];
        }
        __syncthreads();
#pragma unroll
        for (int c = 0; c < 8; c++) {
            float a[4], b[4];
#pragma unroll
            for (int i = 0; i < 4; i++) a[i] = Qs[c][ty * 4 + i];
#pragma unroll
            for (int j = 0; j < 4; j++) b[j] = Ks[c][tx * 4 + j];
#pragma unroll
            for (int i = 0; i < 4; i++)
#pragma unroll
                for (int j = 0; j < 4; j++)
                    acc[i][j] = fmaf(a[i], b[j], acc[i][j]);
        }
    }

#pragma unroll
    for (int i = 0; i < 4; i++) {
        size_t row = (size_t)h * LQ + q0 + ty * 4 + i;
#pragma unroll
        for (int j = 0; j < 4; j++)
            g_S[row * LQ + k0g + tx * 4 + j] = acc[i][j] * SCALE;
    }
}

// ------ per-row stats: exact max, warp-pattern fp32 Z sum ------------------------
__global__ __launch_bounds__(256) void rowred_kernel() {
    int gwarp = (blockIdx.x * 256 + threadIdx.x) >> 5;   // row index
    int lane = threadIdx.x & 31;
    if (gwarp >= NH * LQ) return;
    const float* srow = g_S + (size_t)gwarp * LQ;

    float m = -3.402823466e+38f;
#pragma unroll 4
    for (int j = 0; j < LQ / 32; j++)
        m = fmaxf(m, srow[lane + 32 * j]);
#pragma unroll
    for (int off = 16; off; off >>= 1)
        m = fmaxf(m, __shfl_down_sync(0xffffffffu, m, off));
    m = __shfl_sync(0xffffffffu, m, 0);

    float z = 0.f;
#pragma unroll 4
    for (int j = 0; j < LQ / 32; j++)
        z += expf(srow[lane + 32 * j] - m);
#pragma unroll
    for (int off = 16; off; off >>= 1)
        z += __shfl_down_sync(0xffffffffu, z, off);

    if (lane == 0) {
        g_M[gwarp] = m;
        g_Z[gwarp] = z;
        atomicMin(&g_minZ, __float_as_uint(z));
    }
}

// ---------------- PV: probs from stored S, quantize, multiply V ------------------
__global__ __launch_bounds__(256) void pv_kernel() {
    extern __shared__ float sm[];
    float* Ps = sm;                  // [k 64][q 68]
    float* Vs = sm + 64 * 68;        // [k 64][d 132]
    __shared__ float m_s[64], z_s[64];

    int h = blockIdx.y, q0 = blockIdx.x * 64;
    int tid = threadIdx.x, tx = tid & 15, ty = tid >> 4;

    if (tid < 64) {
        m_s[tid] = g_M[h * LQ + q0 + tid];
        z_s[tid] = g_Z[h * LQ + q0 + tid];
    }
    float maxp = __fdiv_rn(1.0f, __uint_as_float(g_minZ));
    float sP = __fdiv_rn(maxp, 127.0f);

    float o[4][8];
#pragma unroll
    for (int i = 0; i < 4; i++)
#pragma unroll
        for (int j = 0; j < 8; j++) o[i][j] = 0.f;

    const float* Vg = g_Vf + (size_t)h * LQ * HD;

    for (int k0 = 0; k0 < LQ; k0 += 64) {
        __syncthreads();
        for (int i = tid; i < 64 * 64; i += 256) {
            int ql = i >> 6, kl = i & 63;
            float s = g_S[((size_t)h * LQ + q0 + ql) * LQ + k0 + kl];
            float e = expf(s - m_s[ql]);
            float p = __fdiv_rn(e, z_s[ql]);
            float pi = rintf(__fdiv_rn(p, sP));
            pi = fminf(127.f, pi);
            Ps[kl * 68 + ql] = pi * sP;
        }
        for (int i = tid; i < 64 * 32; i += 256) {
            int r = i >> 5, c4 = (i & 31) * 4;
            float4 v = *(const float4*)(Vg + (size_t)(k0 + r) * HD + c4);
            *(float4*)&Vs[r * 132 + c4] = v;
        }
        __syncthreads();

#pragma unroll 4
        for (int k = 0; k < 64; k++) {
            float a[4], b[8];
#pragma unroll
            for (int i = 0; i < 4; i++) a[i] = Ps[k * 68 + ty * 4 + i];
#pragma unroll
            for (int j = 0; j < 8; j++) b[j] = Vs[k * 132 + tx * 8 + j];
#pragma unroll
            for (int i = 0; i < 4; i++)
#pragma unroll
                for (int j = 0; j < 8; j++)
                    o[i][j] = fmaf(a[i], b[j], o[i][j]);
        }
    }

#pragma unroll
    for (int i = 0; i < 4; i++) {
        int row = q0 + ty * 4 + i;
#pragma unroll
        for (int j = 0; j < 8; j++)
            g_attnO[(size_t)row * DIM + h * HD + tx * 8 + j] = o[i][j];
    }
}

// ---------------- output projection: out = attnO @ Wo^T + bias -------------------
__global__ __launch_bounds__(256) void gemm_kernel(
    const float* __restrict__ B, const float* __restrict__ bias,
    float* __restrict__ Cext)
{
    const int N = DIM, K = DIM;
    const float* A = g_attnO;

    __shared__ float As[8][132];
    __shared__ float Bs[8][132];

    int tid = threadIdx.x;
    int tx = tid & 15, ty = tid >> 4;
    int row0 = blockIdx.y * 128, col0 = blockIdx.x * 128;

    int lr = tid >> 1;
    int lc = (tid & 1) * 4;
    const float* Ap = A + (size_t)(row0 + lr) * K + lc;
    const float* Bp = B + (size_t)(col0 + lr) * K + lc;

    float acc[8][8];
#pragma unroll
    for (int i = 0; i < 8; i++)
#pragma unroll
        for (int j = 0; j < 8; j++) acc[i][j] = 0.f;

    for (int k0 = 0; k0 < K; k0 += 8) {
        float4 a4 = *(const float4*)(Ap + k0);
        float4 b4 = *(const float4*)(Bp + k0);
        As[lc + 0][lr] = a4.x; As[lc + 1][lr] = a4.y;
        As[lc + 2][lr] = a4.z; As[lc + 3][lr] = a4.w;
        Bs[lc + 0][lr] = b4.x; Bs[lc + 1][lr] = b4.y;
        Bs[lc + 2][lr] = b4.z; Bs[lc + 3][lr] = b4.w;
        __syncthreads();
#pragma unroll
        for (int kk = 0; kk < 8; kk++) {
            float ra[8], rb[8];
#pragma unroll
            for (int i = 0; i < 8; i++) ra[i] = As[kk][ty * 8 + i];
#pragma unroll
            for (int j = 0; j < 8; j++) rb[j] = Bs[kk][tx * 8 + j];
#pragma unroll
            for (int i = 0; i < 8; i++)
#pragma unroll
                for (int j = 0; j < 8; j++)
                    acc[i][j] = fmaf(ra[i], rb[j], acc[i][j]);
        }
        __syncthreads();
    }

#pragma unroll
    for (int i = 0; i < 8; i++) {
        int r = row0 + ty * 8 + i;
#pragma unroll
        for (int j = 0; j < 8; j++) {
            int c = col0 + tx * 8 + j;
            Cext[(size_t)r * N + c] = acc[i][j] + bias[c];
        }
    }
}

// ---------------- launch ---------------------------------------------------------
extern "C" void kernel_launch(void* const* d_in, const int* in_sizes, int n_in,
                              void* d_out, int out_size) {
    const float* x  = (const float*)d_in[0];
    const float* Wq = (const float*)d_in[1];
    const float* Wk = (const float*)d_in[2];
    const float* Wv = (const float*)d_in[3];
    const float* Wo = (const float*)d_in[4];
    const float* bo = (const float*)d_in[5];
    float* out = (float*)d_out;

    cudaFuncSetAttribute(pv_kernel, cudaFuncAttributeMaxDynamicSharedMemorySize,
                         (64 * 68 + 64 * 132) * 4);

    init_kernel<<<1, 32>>>();

    dim3 gp(DIM / 64, LQ / 128);
    proj_kernel<<<gp, 256>>>(x, Wq, 0);
    proj_kernel<<<gp, 256>>>(x, Wk, 1);
    proj_kernel<<<gp, 256>>>(x, Wv, 2);

    quant_all<<<(NH * LQ * HD) / 256, 256>>>();

    score_kernel<<<dim3(LQ / 64, LQ / 64, NH), 256>>>();
    rowred_kernel<<<(NH * LQ * 32 + 255) / 256, 256>>>();
    pv_kernel<<<dim3(LQ / 64, NH), 256, (64 * 68 + 64 * 132) * 4>>>();

    dim3 g128(DIM / 128, LQ / 128);
    gemm_kernel<<<g128, 256>>>(Wo, bo, out);
}

// round 12
// speedup vs baseline: 1.2289x; 1.2289x over previous
#include <cuda_runtime.h>
#include <cstdint>
#include <cmath>

#define LQ 2048
#define DIM 1536
#define NH 12
#define HD 128
#define SCALE 0.08838834764831845f   // 128^-0.5
#define NSLICE 3
#define KSLICE (DIM / NSLICE)         // 512  (Eigen gebp kc panel)

// ---------------- scratch (static device globals; no allocation) ----------------
__device__ float g_Qf[NH * LQ * HD];
__device__ float g_Kf[NH * LQ * HD];
__device__ float g_Vf[NH * LQ * HD];
__device__ signed char g_Qi8[NH * LQ * HD];
__device__ signed char g_Ki8[NH * LQ * HD];
__device__ signed char g_Vt8[NH * HD * LQ];   // V int8 transposed [h][d][l]
__device__ float g_S[(size_t)NH * LQ * LQ];   // scores, 201MB
__device__ float g_M[NH * LQ];
__device__ float g_Z[NH * LQ];
__device__ float g_attnO[LQ * DIM];
__device__ unsigned int g_amax[4];
__device__ unsigned int g_minZ;

__global__ void init_kernel() {
    if (threadIdx.x < 4) g_amax[threadIdx.x] = 0u;
    if (threadIdx.x == 0) g_minZ = 0x7f800000u;  // +inf
}

// ------ 3-panel fp32 projection (double-buffered): C = A @ B^T -------------------
// Per output element: three serial-ascending fp32 FMA chains over contiguous
// 512-length K panels, combined in panel order (Eigen gebp emulation) —
// numerically identical to R11; only the scheduling changed.
__global__ __launch_bounds__(256) void proj_kernel(
    const float* __restrict__ A, const float* __restrict__ B, int mode)
{
    const int K = DIM;
    __shared__ float As[2][8][132];
    __shared__ float Bs[2][8][68];

    int tid = threadIdx.x;
    int tx = tid & 15, ty = tid >> 4;
    int row0 = blockIdx.y * 128, col0 = blockIdx.x * 64;

    int lr = tid >> 1, lc = (tid & 1) * 4;
    const float* Ap = A + (size_t)(row0 + lr) * K + lc;
    const float* Bp = B + (size_t)(col0 + lr) * K + lc;  // valid for tid<128

    float comb[8][4], acc[8][4];
#pragma unroll
    for (int i = 0; i < 8; i++)
#pragma unroll
        for (int j = 0; j < 4; j++) { comb[i][j] = 0.f; acc[i][j] = 0.f; }

    // preload block 0
    {
        float4 a4 = *(const float4*)Ap;
        As[0][lc + 0][lr] = a4.x; As[0][lc + 1][lr] = a4.y;
        As[0][lc + 2][lr] = a4.z; As[0][lc + 3][lr] = a4.w;
        if (tid < 128) {
            float4 b4 = *(const float4*)Bp;
            Bs[0][lc + 0][lr] = b4.x; Bs[0][lc + 1][lr] = b4.y;
            Bs[0][lc + 2][lr] = b4.z; Bs[0][lc + 3][lr] = b4.w;
        }
    }
    __syncthreads();

    const int nblk = K / 8;   // 192 blocks; panels end at kb = 63,127,191
    for (int kb = 0; kb < nblk; kb++) {
        int cur = kb & 1, nxt = cur ^ 1;
        float4 a4n, b4n;
        bool hn = (kb + 1 < nblk);
        if (hn) {
            a4n = *(const float4*)(Ap + (kb + 1) * 8);
            if (tid < 128) b4n = *(const float4*)(Bp + (kb + 1) * 8);
        }
#pragma unroll
        for (int kk = 0; kk < 8; kk++) {
            float a[8], b[4];
#pragma unroll
            for (int i = 0; i < 8; i++) a[i] = As[cur][kk][ty * 8 + i];
#pragma unroll
            for (int j = 0; j < 4; j++) b[j] = Bs[cur][kk][tx * 4 + j];
#pragma unroll
            for (int i = 0; i < 8; i++)
#pragma unroll
                for (int j = 0; j < 4; j++)
                    acc[i][j] = fmaf(a[i], b[j], acc[i][j]);
        }
        if ((kb & 63) == 63) {   // panel boundary: combine in order, reset
#pragma unroll
            for (int i = 0; i < 8; i++)
#pragma unroll
                for (int j = 0; j < 4; j++) { comb[i][j] += acc[i][j]; acc[i][j] = 0.f; }
        }
        if (hn) {
            As[nxt][lc + 0][lr] = a4n.x; As[nxt][lc + 1][lr] = a4n.y;
            As[nxt][lc + 2][lr] = a4n.z; As[nxt][lc + 3][lr] = a4n.w;
            if (tid < 128) {
                Bs[nxt][lc + 0][lr] = b4n.x; Bs[nxt][lc + 1][lr] = b4n.y;
                Bs[nxt][lc + 2][lr] = b4n.z; Bs[nxt][lc + 3][lr] = b4n.w;
            }
        }
        __syncthreads();
    }

    float* dst = (mode == 0) ? g_Qf : (mode == 1) ? g_Kf : g_Vf;
    float lmax = 0.f;
#pragma unroll
    for (int i = 0; i < 8; i++) {
        int r = row0 + ty * 8 + i;
#pragma unroll
        for (int j = 0; j < 4; j++) {
            int c = col0 + tx * 4 + j;
            float v = comb[i][j];
            int h = c >> 7, d = c & 127;
            dst[((size_t)h * LQ + r) * HD + d] = v;
            lmax = fmaxf(lmax, fabsf(v));
        }
    }
#pragma unroll
    for (int off = 16; off; off >>= 1)
        lmax = fmaxf(lmax, __shfl_xor_sync(0xffffffffu, lmax, off));
    if ((tid & 31) == 0)
        atomicMax(&g_amax[mode], __float_as_uint(lmax));
}

// ------- quantize Q,K to int8 (IEEE RN divide, round-half-even) ------------------
__global__ void quant_qk() {
    float sQ = __fdiv_rn(__uint_as_float(g_amax[0]), 127.0f);
    float sK = __fdiv_rn(__uint_as_float(g_amax[1]), 127.0f);
    int idx = blockIdx.x * 256 + threadIdx.x;

    float qi = rintf(__fdiv_rn(g_Qf[idx], sQ));
    qi = fmaxf(-128.f, fminf(127.f, qi));
    g_Qi8[idx] = (signed char)(int)qi;

    float ki = rintf(__fdiv_rn(g_Kf[idx], sK));
    ki = fmaxf(-128.f, fminf(127.f, ki));
    g_Ki8[idx] = (signed char)(int)ki;
}

// ------- quantize V to int8 + transpose to [h][d][l] ------------------------------
__global__ void quant_v() {
    __shared__ signed char t[32][33];
    int h = blockIdx.z;
    int l0 = blockIdx.x * 32, d0 = blockIdx.y * 32;
    int tx = threadIdx.x, ty = threadIdx.y;
    float sV = __fdiv_rn(__uint_as_float(g_amax[2]), 127.0f);
    float v = g_Vf[((size_t)h * LQ + l0 + ty) * HD + d0 + tx];
    float vi = rintf(__fdiv_rn(v, sV));
    vi = fmaxf(-128.f, fminf(127.f, vi));
    t[ty][tx] = (signed char)(int)vi;
    __syncthreads();
    g_Vt8[((size_t)h * HD + d0 + ty) * LQ + l0 + tx] = t[tx][ty];
}

// ------ scores via exact int8 DP4A: S = (qi @ ki^T) * (sQ*sK*SCALE) ---------------
// 128x128 tile, 256 threads, 8x8/thread, d packed 4/word (32 words)
__global__ __launch_bounds__(256) void score_i8() {
    __shared__ int Qw[32][132];
    __shared__ int Kw[32][132];

    int h = blockIdx.z;
    int q0 = blockIdx.y * 128, k0 = blockIdx.x * 128;
    int tid = threadIdx.x, tx = tid & 15, ty = tid >> 4;

    const uint4* Qg = (const uint4*)(g_Qi8 + ((size_t)h * LQ + q0) * HD);
    const uint4* Kg = (const uint4*)(g_Ki8 + ((size_t)h * LQ + k0) * HD);

#pragma unroll
    for (int it = 0; it < 4; it++) {
        int idx = it * 256 + tid;
        int r = idx >> 3, sg = idx & 7;
        uint4 a = Qg[(size_t)r * 8 + sg];
        Qw[sg * 4 + 0][r] = a.x; Qw[sg * 4 + 1][r] = a.y;
        Qw[sg * 4 + 2][r] = a.z; Qw[sg * 4 + 3][r] = a.w;
        uint4 b = Kg[(size_t)r * 8 + sg];
        Kw[sg * 4 + 0][r] = b.x; Kw[sg * 4 + 1][r] = b.y;
        Kw[sg * 4 + 2][r] = b.z; Kw[sg * 4 + 3][r] = b.w;
    }
    __syncthreads();

    int acc[8][8];
#pragma unroll
    for (int i = 0; i < 8; i++)
#pragma unroll
        for (int j = 0; j < 8; j++) acc[i][j] = 0;

#pragma unroll 4
    for (int w = 0; w < 32; w++) {
        int a[8], b[8];
#pragma unroll
        for (int i = 0; i < 8; i++) a[i] = Qw[w][ty * 8 + i];
#pragma unroll
        for (int j = 0; j < 8; j++) b[j] = Kw[w][tx * 8 + j];
#pragma unroll
        for (int i = 0; i < 8; i++)
#pragma unroll
            for (int j = 0; j < 8; j++)
                acc[i][j] = __dp4a(a[i], b[j], acc[i][j]);
    }

    float sQ = __fdiv_rn(__uint_as_float(g_amax[0]), 127.0f);
    float sK = __fdiv_rn(__uint_as_float(g_amax[1]), 127.0f);
    float c = (float)((double)sQ * (double)sK * (double)SCALE);
#pragma unroll
    for (int i = 0; i < 8; i++) {
        size_t row = (size_t)h * LQ + q0 + ty * 8 + i;
#pragma unroll
        for (int j = 0; j < 8; j++)
            g_S[row * LQ + k0 + tx * 8 + j] = (float)acc[i][j] * c;
    }
}

// ------ per-row stats: exact max, warp-pattern fp32 Z sum ------------------------
__global__ __launch_bounds__(256) void rowred_kernel() {
    int gwarp = (blockIdx.x * 256 + threadIdx.x) >> 5;
    int lane = threadIdx.x & 31;
    if (gwarp >= NH * LQ) return;
    const float* srow = g_S + (size_t)gwarp * LQ;

    float m = -3.402823466e+38f;
#pragma unroll 4
    for (int j = 0; j < LQ / 32; j++)
        m = fmaxf(m, srow[lane + 32 * j]);
#pragma unroll
    for (int off = 16; off; off >>= 1)
        m = fmaxf(m, __shfl_down_sync(0xffffffffu, m, off));
    m = __shfl_sync(0xffffffffu, m, 0);

    float z = 0.f;
#pragma unroll 4
    for (int j = 0; j < LQ / 32; j++)
        z += expf(srow[lane + 32 * j] - m);
#pragma unroll
    for (int off = 16; off; off >>= 1)
        z += __shfl_down_sync(0xffffffffu, z, off);

    if (lane == 0) {
        g_M[gwarp] = m;
        g_Z[gwarp] = z;
        atomicMin(&g_minZ, __float_as_uint(z));
    }
}

// ------ PV via exact int8 DP4A: probs quantized on the fly -----------------------
// 64q x 128d per block, 256 threads (4q x 8d each), k-blocks of 128
__global__ __launch_bounds__(256) void pv_i8() {
    __shared__ int Pw[32][68];     // [kw][q]
    __shared__ int Vw[32][132];    // [kw][d]
    __shared__ float m_s[64], z_s[64];

    int h = blockIdx.y, q0 = blockIdx.x * 64;
    int tid = threadIdx.x, tx = tid & 15, ty = tid >> 4;

    if (tid < 64) {
        m_s[tid] = g_M[h * LQ + q0 + tid];
        z_s[tid] = g_Z[h * LQ + q0 + tid];
    }
    float maxp = __fdiv_rn(1.0f, __uint_as_float(g_minZ));
    float sP = __fdiv_rn(maxp, 127.0f);
    float sV = __fdiv_rn(__uint_as_float(g_amax[2]), 127.0f);
    float cPV = (float)((double)sP * (double)sV);
    __syncthreads();

    int o[4][8];
#pragma unroll
    for (int i = 0; i < 4; i++)
#pragma unroll
        for (int j = 0; j < 8; j++) o[i][j] = 0;

    const uint4* Vg = (const uint4*)(g_Vt8 + (size_t)h * HD * LQ);

    for (int k0 = 0; k0 < LQ; k0 += 128) {
        __syncthreads();   // previous dp4a reads done before overwrite
        // probs: 64q x 128k -> packed words Pw[kw][q]
#pragma unroll
        for (int it = 0; it < 8; it++) {
            int idx = it * 256 + tid;
            int q = idx >> 5, kw = idx & 31;
            float4 s4 = *(const float4*)(g_S + ((size_t)h * LQ + q0 + q) * LQ + k0 + kw * 4);
            float m = m_s[q], z = z_s[q];
            float f0 = fminf(127.f, rintf(__fdiv_rn(__fdiv_rn(expf(s4.x - m), z), sP)));
            float f1 = fminf(127.f, rintf(__fdiv_rn(__fdiv_rn(expf(s4.y - m), z), sP)));
            float f2 = fminf(127.f, rintf(__fdiv_rn(__fdiv_rn(expf(s4.z - m), z), sP)));
            float f3 = fminf(127.f, rintf(__fdiv_rn(__fdiv_rn(expf(s4.w - m), z), sP)));
            Pw[kw][q] = (int)f0 | ((int)f1 << 8) | ((int)f2 << 16) | ((int)f3 << 24);
        }
        // V tile: 128d x 128k bytes -> Vw[kw][d]
#pragma unroll
        for (int it = 0; it < 4; it++) {
            int idx = it * 256 + tid;
            int d = idx >> 3, sg = idx & 7;
            uint4 v = Vg[(size_t)d * (LQ / 16) + (k0 / 16) + sg];
            Vw[sg * 4 + 0][d] = v.x; Vw[sg * 4 + 1][d] = v.y;
            Vw[sg * 4 + 2][d] = v.z; Vw[sg * 4 + 3][d] = v.w;
        }
        __syncthreads();

#pragma unroll 4
        for (int kw = 0; kw < 32; kw++) {
            int a[4], b[8];
#pragma unroll
            for (int i = 0; i < 4; i++) a[i] = Pw[kw][ty * 4 + i];
#pragma unroll
            for (int j = 0; j < 8; j++) b[j] = Vw[kw][tx * 8 + j];
#pragma unroll
            for (int i = 0; i < 4; i++)
#pragma unroll
                for (int j = 0; j < 8; j++)
                    o[i][j] = __dp4a(a[i], b[j], o[i][j]);
        }
    }

#pragma unroll
    for (int i = 0; i < 4; i++) {
        int row = q0 + ty * 4 + i;
#pragma unroll
        for (int j = 0; j < 8; j++)
            g_attnO[(size_t)row * DIM + h * HD + tx * 8 + j] = (float)o[i][j] * cPV;
    }
}

// ---------------- output projection (double-buffered): out = attnO @ Wo^T + bias --
__global__ __launch_bounds__(256) void gemm_kernel(
    const float* __restrict__ B, const float* __restrict__ bias,
    float* __restrict__ Cext)
{
    const int N = DIM, K = DIM;
    const float* A = g_attnO;

    __shared__ float As[2][8][132];
    __shared__ float Bs[2][8][132];

    int tid = threadIdx.x;
    int tx = tid & 15, ty = tid >> 4;
    int row0 = blockIdx.y * 128, col0 = blockIdx.x * 128;

    int lr = tid >> 1, lc = (tid & 1) * 4;
    const float* Ap = A + (size_t)(row0 + lr) * K + lc;
    const float* Bp = B + (size_t)(col0 + lr) * K + lc;

    float acc[8][8];
#pragma unroll
    for (int i = 0; i < 8; i++)
#pragma unroll
        for (int j = 0; j < 8; j++) acc[i][j] = 0.f;

    {
        float4 a4 = *(const float4*)Ap;
        float4 b4 = *(const float4*)Bp;
        As[0][lc + 0][lr] = a4.x; As[0][lc + 1][lr] = a4.y;
        As[0][lc + 2][lr] = a4.z; As[0][lc + 3][lr] = a4.w;
        Bs[0][lc + 0][lr] = b4.x; Bs[0][lc + 1][lr] = b4.y;
        Bs[0][lc + 2][lr] = b4.z; Bs[0][lc + 3][lr] = b4.w;
    }
    __syncthreads();

    const int nblk = K / 8;
    for (int kb = 0; kb < nblk; kb++) {
        int cur = kb & 1, nxt = cur ^ 1;
        float4 a4n, b4n;
        bool hn = (kb + 1 < nblk);
        if (hn) {
            a4n = *(const float4*)(Ap + (kb + 1) * 8);
            b4n = *(const float4*)(Bp + (kb + 1) * 8);
        }
#pragma unroll
        for (int kk = 0; kk < 8; kk++) {
            float ra[8], rb[8];
#pragma unroll
            for (int i = 0; i < 8; i++) ra[i] = As[cur][kk][ty * 8 + i];
#pragma unroll
            for (int j = 0; j < 8; j++) rb[j] = Bs[cur][kk][tx * 8 + j];
#pragma unroll
            for (int i = 0; i < 8; i++)
#pragma unroll
                for (int j = 0; j < 8; j++)
                    acc[i][j] = fmaf(ra[i], rb[j], acc[i][j]);
        }
        if (hn) {
            As[nxt][lc + 0][lr] = a4n.x; As[nxt][lc + 1][lr] = a4n.y;
            As[nxt][lc + 2][lr] = a4n.z; As[nxt][lc + 3][lr] = a4n.w;
            Bs[nxt][lc + 0][lr] = b4n.x; Bs[nxt][lc + 1][lr] = b4n.y;
            Bs[nxt][lc + 2][lr] = b4n.z; Bs[nxt][lc + 3][lr] = b4n.w;
        }
        __syncthreads();
    }

#pragma unroll
    for (int i = 0; i < 8; i++) {
        int r = row0 + ty * 8 + i;
#pragma unroll
        for (int j = 0; j < 8; j++) {
            int c = col0 + tx * 8 + j;
            Cext[(size_t)r * N + c] = acc[i][j] + bias[c];
        }
    }
}

// ---------------- launch ---------------------------------------------------------
extern "C" void kernel_launch(void* const* d_in, const int* in_sizes, int n_in,
                              void* d_out, int out_size) {
    const float* x  = (const float*)d_in[0];
    const float* Wq = (const float*)d_in[1];
    const float* Wk = (const float*)d_in[2];
    const float* Wv = (const float*)d_in[3];
    const float* Wo = (const float*)d_in[4];
    const float* bo = (const float*)d_in[5];
    float* out = (float*)d_out;

    init_kernel<<<1, 32>>>();

    dim3 gp(DIM / 64, LQ / 128);
    proj_kernel<<<gp, 256>>>(x, Wq, 0);
    proj_kernel<<<gp, 256>>>(x, Wk, 1);
    proj_kernel<<<gp, 256>>>(x, Wv, 2);

    quant_qk<<<(NH * LQ * HD) / 256, 256>>>();
    quant_v<<<dim3(LQ / 32, HD / 32, NH), dim3(32, 32)>>>();

    score_i8<<<dim3(LQ / 128, LQ / 128, NH), 256>>>();
    rowred_kernel<<<(NH * LQ * 32 + 255) / 256, 256>>>();
    pv_i8<<<dim3(LQ / 64, NH), 256>>>();

    dim3 g128(DIM / 128, LQ / 128);
    gemm_kernel<<<g128, 256>>>(Wo, bo, out);
}

// round 13
// speedup vs baseline: 1.4697x; 1.1959x over previous
#include <cuda_runtime.h>
#include <cstdint>
#include <cmath>

#define LQ 2048
#define DIM 1536
#define NH 12
#define HD 128
#define SCALE 0.08838834764831845f   // 128^-0.5
#define NSLICE 3
#define KSLICE (DIM / NSLICE)         // 512  (Eigen gebp kc panel)

// ---------------- scratch (static device globals; no allocation) ----------------
__device__ float g_Qf[NH * LQ * HD];
__device__ float g_Kf[NH * LQ * HD];
__device__ float g_Vf[NH * LQ * HD];
__device__ signed char g_Qi8[NH * LQ * HD];
__device__ signed char g_Ki8[NH * LQ * HD];
__device__ signed char g_Vt8[NH * HD * LQ];   // V int8 transposed [h][d][l]
__device__ float g_S[(size_t)NH * LQ * LQ];   // scores, 201MB
__device__ float g_M[NH * LQ];
__device__ float g_Z[NH * LQ];
__device__ float g_attnO[LQ * DIM];
__device__ unsigned int g_amax[4];
__device__ unsigned int g_minZ;

__global__ void init_kernel() {
    if (threadIdx.x < 4) g_amax[threadIdx.x] = 0u;
    if (threadIdx.x == 0) g_minZ = 0x7f800000u;  // +inf
}

// ------ fused 3-panel fp32 projections: {Q,K,V} = x @ {Wq,Wk,Wv}^T ---------------
// grid (DIM/64, LQ/128, 3); z selects weight/destination. Per output element:
// three serial-ascending fp32 FMA chains over contiguous 512-length K panels,
// combined in panel order (Eigen gebp emulation) — bit-identical to R11/R12.
__global__ __launch_bounds__(256) void proj_kernel(
    const float* __restrict__ A, const float* __restrict__ B0,
    const float* __restrict__ B1, const float* __restrict__ B2)
{
    const int K = DIM;
    int mode = blockIdx.z;
    const float* B = (mode == 0) ? B0 : (mode == 1) ? B1 : B2;

    __shared__ float As[8][132];
    __shared__ float Bs[8][68];

    int tid = threadIdx.x;
    int tx = tid & 15, ty = tid >> 4;
    int row0 = blockIdx.y * 128, col0 = blockIdx.x * 64;

    int lr = tid >> 1, lc = (tid & 1) * 4;
    const float* Ap = A + (size_t)(row0 + lr) * K + lc;
    const float* Bp = B + (size_t)(col0 + lr) * K + lc;   // valid for tid<128

    float comb[8][4], acc[8][4];

#pragma unroll 1
    for (int s = 0; s < NSLICE; s++) {
#pragma unroll
        for (int i = 0; i < 8; i++)
#pragma unroll
            for (int j = 0; j < 4; j++) acc[i][j] = 0.f;

        int kbeg = s * KSLICE, kend = kbeg + KSLICE;
        for (int k0 = kbeg; k0 < kend; k0 += 8) {
            __syncthreads();
            {
                float4 a4 = *(const float4*)(Ap + k0);
                As[lc + 0][lr] = a4.x; As[lc + 1][lr] = a4.y;
                As[lc + 2][lr] = a4.z; As[lc + 3][lr] = a4.w;
            }
            if (tid < 128) {
                float4 b4 = *(const float4*)(Bp + k0);
                Bs[lc + 0][lr] = b4.x; Bs[lc + 1][lr] = b4.y;
                Bs[lc + 2][lr] = b4.z; Bs[lc + 3][lr] = b4.w;
            }
            __syncthreads();
#pragma unroll
            for (int kk = 0; kk < 8; kk++) {
                float a[8], b[4];
#pragma unroll
                for (int i = 0; i < 8; i++) a[i] = As[kk][ty * 8 + i];
#pragma unroll
                for (int j = 0; j < 4; j++) b[j] = Bs[kk][tx * 4 + j];
#pragma unroll
                for (int i = 0; i < 8; i++)
#pragma unroll
                    for (int j = 0; j < 4; j++)
                        acc[i][j] = fmaf(a[i], b[j], acc[i][j]);
            }
        }

        if (s == 0) {
#pragma unroll
            for (int i = 0; i < 8; i++)
#pragma unroll
                for (int j = 0; j < 4; j++) comb[i][j] = acc[i][j];
        } else {
#pragma unroll
            for (int i = 0; i < 8; i++)
#pragma unroll
                for (int j = 0; j < 4; j++) comb[i][j] += acc[i][j];
        }
    }

    float* dst = (mode == 0) ? g_Qf : (mode == 1) ? g_Kf : g_Vf;
    float lmax = 0.f;
#pragma unroll
    for (int i = 0; i < 8; i++) {
        int r = row0 + ty * 8 + i;
#pragma unroll
        for (int j = 0; j < 4; j++) {
            int c = col0 + tx * 4 + j;
            float v = comb[i][j];
            int h = c >> 7, d = c & 127;
            dst[((size_t)h * LQ + r) * HD + d] = v;
            lmax = fmaxf(lmax, fabsf(v));
        }
    }
#pragma unroll
    for (int off = 16; off; off >>= 1)
        lmax = fmaxf(lmax, __shfl_xor_sync(0xffffffffu, lmax, off));
    if ((tid & 31) == 0)
        atomicMax(&g_amax[mode], __float_as_uint(lmax));
}

// ------- quantize Q,K to int8 (IEEE RN divide, round-half-even) ------------------
__global__ void quant_qk() {
    float sQ = __fdiv_rn(__uint_as_float(g_amax[0]), 127.0f);
    float sK = __fdiv_rn(__uint_as_float(g_amax[1]), 127.0f);
    int idx = blockIdx.x * 256 + threadIdx.x;

    float qi = rintf(__fdiv_rn(g_Qf[idx], sQ));
    qi = fmaxf(-128.f, fminf(127.f, qi));
    g_Qi8[idx] = (signed char)(int)qi;

    float ki = rintf(__fdiv_rn(g_Kf[idx], sK));
    ki = fmaxf(-128.f, fminf(127.f, ki));
    g_Ki8[idx] = (signed char)(int)ki;
}

// ------- quantize V to int8 + transpose to [h][d][l] ------------------------------
__global__ void quant_v() {
    __shared__ signed char t[32][33];
    int h = blockIdx.z;
    int l0 = blockIdx.x * 32, d0 = blockIdx.y * 32;
    int tx = threadIdx.x, ty = threadIdx.y;
    float sV = __fdiv_rn(__uint_as_float(g_amax[2]), 127.0f);
    float v = g_Vf[((size_t)h * LQ + l0 + ty) * HD + d0 + tx];
    float vi = rintf(__fdiv_rn(v, sV));
    vi = fmaxf(-128.f, fminf(127.f, vi));
    t[ty][tx] = (signed char)(int)vi;
    __syncthreads();
    g_Vt8[((size_t)h * HD + d0 + ty) * LQ + l0 + tx] = t[tx][ty];
}

// ------ scores via exact int8 DP4A: S = (qi @ ki^T) * (sQ*sK*SCALE) ---------------
__global__ __launch_bounds__(256) void score_i8() {
    __shared__ int Qw[32][132];
    __shared__ int Kw[32][132];

    int h = blockIdx.z;
    int q0 = blockIdx.y * 128, k0 = blockIdx.x * 128;
    int tid = threadIdx.x, tx = tid & 15, ty = tid >> 4;

    const uint4* Qg = (const uint4*)(g_Qi8 + ((size_t)h * LQ + q0) * HD);
    const uint4* Kg = (const uint4*)(g_Ki8 + ((size_t)h * LQ + k0) * HD);

#pragma unroll
    for (int it = 0; it < 4; it++) {
        int idx = it * 256 + tid;
        int r = idx >> 3, sg = idx & 7;
        uint4 a = Qg[(size_t)r * 8 + sg];
        Qw[sg * 4 + 0][r] = a.x; Qw[sg * 4 + 1][r] = a.y;
        Qw[sg * 4 + 2][r] = a.z; Qw[sg * 4 + 3][r] = a.w;
        uint4 b = Kg[(size_t)r * 8 + sg];
        Kw[sg * 4 + 0][r] = b.x; Kw[sg * 4 + 1][r] = b.y;
        Kw[sg * 4 + 2][r] = b.z; Kw[sg * 4 + 3][r] = b.w;
    }
    __syncthreads();

    int acc[8][8];
#pragma unroll
    for (int i = 0; i < 8; i++)
#pragma unroll
        for (int j = 0; j < 8; j++) acc[i][j] = 0;

#pragma unroll 4
    for (int w = 0; w < 32; w++) {
        int a[8], b[8];
#pragma unroll
        for (int i = 0; i < 8; i++) a[i] = Qw[w][ty * 8 + i];
#pragma unroll
        for (int j = 0; j < 8; j++) b[j] = Kw[w][tx * 8 + j];
#pragma unroll
        for (int i = 0; i < 8; i++)
#pragma unroll
            for (int j = 0; j < 8; j++)
                acc[i][j] = __dp4a(a[i], b[j], acc[i][j]);
    }

    float sQ = __fdiv_rn(__uint_as_float(g_amax[0]), 127.0f);
    float sK = __fdiv_rn(__uint_as_float(g_amax[1]), 127.0f);
    float c = (float)((double)sQ * (double)sK * (double)SCALE);
#pragma unroll
    for (int i = 0; i < 8; i++) {
        size_t row = (size_t)h * LQ + q0 + ty * 8 + i;
#pragma unroll
        for (int j = 0; j < 8; j++)
            g_S[row * LQ + k0 + tx * 8 + j] = (float)acc[i][j] * c;
    }
}

// ------ per-row stats: exact max, warp-pattern fp32 Z sum ------------------------
__global__ __launch_bounds__(256) void rowred_kernel() {
    int gwarp = (blockIdx.x * 256 + threadIdx.x) >> 5;
    int lane = threadIdx.x & 31;
    if (gwarp >= NH * LQ) return;
    const float* srow = g_S + (size_t)gwarp * LQ;

    float m = -3.402823466e+38f;
#pragma unroll 4
    for (int j = 0; j < LQ / 32; j++)
        m = fmaxf(m, srow[lane + 32 * j]);
#pragma unroll
    for (int off = 16; off; off >>= 1)
        m = fmaxf(m, __shfl_down_sync(0xffffffffu, m, off));
    m = __shfl_sync(0xffffffffu, m, 0);

    float z = 0.f;
#pragma unroll 4
    for (int j = 0; j < LQ / 32; j++)
        z += expf(srow[lane + 32 * j] - m);
#pragma unroll
    for (int off = 16; off; off >>= 1)
        z += __shfl_down_sync(0xffffffffu, z, off);

    if (lane == 0) {
        g_M[gwarp] = m;
        g_Z[gwarp] = z;
        atomicMin(&g_minZ, __float_as_uint(z));
    }
}

// ------ PV via exact int8 DP4A: probs quantized on the fly -----------------------
__global__ __launch_bounds__(256) void pv_i8() {
    __shared__ int Pw[32][68];     // [kw][q]
    __shared__ int Vw[32][132];    // [kw][d]
    __shared__ float m_s[64], z_s[64];

    int h = blockIdx.y, q0 = blockIdx.x * 64;
    int tid = threadIdx.x, tx = tid & 15, ty = tid >> 4;

    if (tid < 64) {
        m_s[tid] = g_M[h * LQ + q0 + tid];
        z_s[tid] = g_Z[h * LQ + q0 + tid];
    }
    float maxp = __fdiv_rn(1.0f, __uint_as_float(g_minZ));
    float sP = __fdiv_rn(maxp, 127.0f);
    float sV = __fdiv_rn(__uint_as_float(g_amax[2]), 127.0f);
    float cPV = (float)((double)sP * (double)sV);
    __syncthreads();

    int o[4][8];
#pragma unroll
    for (int i = 0; i < 4; i++)
#pragma unroll
        for (int j = 0; j < 8; j++) o[i][j] = 0;

    const uint4* Vg = (const uint4*)(g_Vt8 + (size_t)h * HD * LQ);

    for (int k0 = 0; k0 < LQ; k0 += 128) {
        __syncthreads();
#pragma unroll
        for (int it = 0; it < 8; it++) {
            int idx = it * 256 + tid;
            int q = idx >> 5, kw = idx & 31;
            float4 s4 = *(const float4*)(g_S + ((size_t)h * LQ + q0 + q) * LQ + k0 + kw * 4);
            float m = m_s[q], z = z_s[q];
            float f0 = fminf(127.f, rintf(__fdiv_rn(__fdiv_rn(expf(s4.x - m), z), sP)));
            float f1 = fminf(127.f, rintf(__fdiv_rn(__fdiv_rn(expf(s4.y - m), z), sP)));
            float f2 = fminf(127.f, rintf(__fdiv_rn(__fdiv_rn(expf(s4.z - m), z), sP)));
            float f3 = fminf(127.f, rintf(__fdiv_rn(__fdiv_rn(expf(s4.w - m), z), sP)));
            Pw[kw][q] = (int)f0 | ((int)f1 << 8) | ((int)f2 << 16) | ((int)f3 << 24);
        }
#pragma unroll
        for (int it = 0; it < 4; it++) {
            int idx = it * 256 + tid;
            int d = idx >> 3, sg = idx & 7;
            uint4 v = Vg[(size_t)d * (LQ / 16) + (k0 / 16) + sg];
            Vw[sg * 4 + 0][d] = v.x; Vw[sg * 4 + 1][d] = v.y;
            Vw[sg * 4 + 2][d] = v.z; Vw[sg * 4 + 3][d] = v.w;
        }
        __syncthreads();

#pragma unroll 4
        for (int kw = 0; kw < 32; kw++) {
            int a[4], b[8];
#pragma unroll
            for (int i = 0; i < 4; i++) a[i] = Pw[kw][ty * 4 + i];
#pragma unroll
            for (int j = 0; j < 8; j++) b[j] = Vw[kw][tx * 8 + j];
#pragma unroll
            for (int i = 0; i < 4; i++)
#pragma unroll
                for (int j = 0; j < 8; j++)
                    o[i][j] = __dp4a(a[i], b[j], o[i][j]);
        }
    }

#pragma unroll
    for (int i = 0; i < 4; i++) {
        int row = q0 + ty * 4 + i;
#pragma unroll
        for (int j = 0; j < 8; j++)
            g_attnO[(size_t)row * DIM + h * HD + tx * 8 + j] = (float)o[i][j] * cPV;
    }
}

// ---------------- output projection (single-buffer): out = attnO @ Wo^T + bias ---
__global__ __launch_bounds__(256) void gemm_kernel(
    const float* __restrict__ B, const float* __restrict__ bias,
    float* __restrict__ Cext)
{
    const int N = DIM, K = DIM;
    const float* A = g_attnO;

    __shared__ float As[8][132];
    __shared__ float Bs[8][132];

    int tid = threadIdx.x;
    int tx = tid & 15, ty = tid >> 4;
    int row0 = blockIdx.y * 128, col0 = blockIdx.x * 128;

    int lr = tid >> 1, lc = (tid & 1) * 4;
    const float* Ap = A + (size_t)(row0 + lr) * K + lc;
    const float* Bp = B + (size_t)(col0 + lr) * K + lc;

    float acc[8][8];
#pragma unroll
    for (int i = 0; i < 8; i++)
#pragma unroll
        for (int j = 0; j < 8; j++) acc[i][j] = 0.f;

    for (int k0 = 0; k0 < K; k0 += 8) {
        float4 a4 = *(const float4*)(Ap + k0);
        float4 b4 = *(const float4*)(Bp + k0);
        As[lc + 0][lr] = a4.x; As[lc + 1][lr] = a4.y;
        As[lc + 2][lr] = a4.z; As[lc + 3][lr] = a4.w;
        Bs[lc + 0][lr] = b4.x; Bs[lc + 1][lr] = b4.y;
        Bs[lc + 2][lr] = b4.z; Bs[lc + 3][lr] = b4.w;
        __syncthreads();
#pragma unroll
        for (int kk = 0; kk < 8; kk++) {
            float ra[8], rb[8];
#pragma unroll
            for (int i = 0; i < 8; i++) ra[i] = As[kk][ty * 8 + i];
#pragma unroll
            for (int j = 0; j < 8; j++) rb[j] = Bs[kk][tx * 8 + j];
#pragma unroll
            for (int i = 0; i < 8; i++)
#pragma unroll
                for (int j = 0; j < 8; j++)
                    acc[i][j] = fmaf(ra[i], rb[j], acc[i][j]);
        }
        __syncthreads();
    }

#pragma unroll
    for (int i = 0; i < 8; i++) {
        int r = row0 + ty * 8 + i;
#pragma unroll
        for (int j = 0; j < 8; j++) {
            int c = col0 + tx * 8 + j;
            Cext[(size_t)r * N + c] = acc[i][j] + bias[c];
        }
    }
}

// ---------------- launch ---------------------------------------------------------
extern "C" void kernel_launch(void* const* d_in, const int* in_sizes, int n_in,
                              void* d_out, int out_size) {
    const float* x  = (const float*)d_in[0];
    const float* Wq = (const float*)d_in[1];
    const float* Wk = (const float*)d_in[2];
    const float* Wv = (const float*)d_in[3];
    const float* Wo = (const float*)d_in[4];
    const float* bo = (const float*)d_in[5];
    float* out = (float*)d_out;

    init_kernel<<<1, 32>>>();

    dim3 gp(DIM / 64, LQ / 128, 3);
    proj_kernel<<<gp, 256>>>(x, Wq, Wk, Wv);

    quant_qk<<<(NH * LQ * HD) / 256, 256>>>();
    quant_v<<<dim3(LQ / 32, HD / 32, NH), dim3(32, 32)>>>();

    score_i8<<<dim3(LQ / 128, LQ / 128, NH), 256>>>();
    rowred_kernel<<<(NH * LQ * 32 + 255) / 256, 256>>>();
    pv_i8<<<dim3(LQ / 64, NH), 256>>>();

    dim3 g128(DIM / 128, LQ / 128);
    gemm_kernel<<<g128, 256>>>(Wo, bo, out);
}